// round 16
// baseline (speedup 1.0000x reference)
#include <cuda_runtime.h>
#include <cstdint>

#define DMODEL 768
#define NH     12
#define DH     64
#define WIN    16
#define NWIN   128
#define BB     2
#define TT     2048
#define IGNORE_V (-1.0e6f)

// Scratch (device globals: allocation-free)
__device__ float g_abcde[(size_t)BB * TT * 5 * NH * DH]; // 62.9 MB
__device__ float g_xp[(size_t)BB * TT * DMODEL];         // x packed (A-frag)
__device__ float g_zp[(size_t)BB * TT * DMODEL];         // z packed (A-frag), written by attn
__device__ float g_w1p[(size_t)DMODEL * 5 * NH * DH];    // W1 packed (B-pair-frag)
__device__ float g_wop[(size_t)DMODEL * DMODEL];         // WO packed (B-pair-frag)

// ---------------------------------------------------------------------------
__device__ __forceinline__ unsigned f2tf32(float x) {
    unsigned r;
    asm("cvt.rna.tf32.f32 %0, %1;" : "=r"(r) : "f"(x));
    return r;
}
__device__ __forceinline__ unsigned smem_u32(const void* p) {
    unsigned a;
    asm("{ .reg .u64 t; cvta.to.shared.u64 t, %1; cvt.u32.u64 %0, t; }" : "=r"(a) : "l"(p));
    return a;
}
__device__ __forceinline__ void cp16(void* s, const void* g) {
    asm volatile("cp.async.cg.shared.global [%0], [%1], 16;"
                 :: "r"(smem_u32(s)), "l"(g) : "memory");
}
__device__ __forceinline__ void mma_tf32(float c[4], const unsigned a[4], const unsigned b[2]) {
    asm volatile(
        "mma.sync.aligned.m16n8k8.row.col.f32.tf32.tf32.f32 "
        "{%0,%1,%2,%3}, {%4,%5,%6,%7}, {%8,%9}, {%0,%1,%2,%3};"
        : "+f"(c[0]), "+f"(c[1]), "+f"(c[2]), "+f"(c[3])
        : "r"(a[0]), "r"(a[1]), "r"(a[2]), "r"(a[3]), "r"(b[0]), "r"(b[1]));
}

// ---------------------------------------------------------------------------
// pack bodies
// ---------------------------------------------------------------------------
__device__ __forceinline__ void pack_a_body(const float* __restrict__ in,
                                            float* __restrict__ out,
                                            int K, int nks, int ks, int stripe, int tid)
{
    const int i = tid >> 5, lane = tid & 31;
    const int g = lane >> 2, t = lane & 3;
    const int row = stripe * 128 + i * 16 + g;
    const int col = ks * 8 + t;
    const float* p = in + (size_t)row * K + col;
    uint4 o;
    o.x = f2tf32(p[0]);
    o.y = f2tf32(p[(size_t)8 * K]);
    o.z = f2tf32(p[4]);
    o.w = f2tf32(p[(size_t)8 * K + 4]);
    ((uint4*)out)[((size_t)(stripe * nks + ks) * 8 + i) * 32 + lane] = o;
}

__device__ __forceinline__ void pack_b_body(const float* __restrict__ in,
                                            float* __restrict__ out,
                                            int N, int nks, int ks, int cb, int tid)
{
    const int jp = tid >> 5, lane = tid & 31;
    const int g = lane >> 2, t = lane & 3;
    const int k  = ks * 8 + t;
    const int n0 = cb * 128 + jp * 16 + g;
    uint4 o;
    o.x = f2tf32(in[(size_t)k * N + n0]);
    o.y = f2tf32(in[(size_t)(k + 4) * N + n0]);
    o.z = f2tf32(in[(size_t)k * N + n0 + 8]);
    o.w = f2tf32(in[(size_t)(k + 4) * N + n0 + 8]);
    ((uint4*)out)[((size_t)(cb * nks + ks) * 8 + jp) * 32 + lane] = o;
}

__global__ __launch_bounds__(256)
void pack_all(const float* __restrict__ x, const float* __restrict__ W1,
              const float* __restrict__ WO)
{
    const int blk = blockIdx.x;
    const int tid = threadIdx.x;
    if (blk < 3072) {
        pack_a_body(x, g_xp, DMODEL, 96, blk % 96, blk / 96, tid);
    } else if (blk < 3072 + 2880) {
        const int idx = blk - 3072;
        pack_b_body(W1, g_w1p, 5 * NH * DH, 96, idx % 96, idx / 96, tid);
    } else {
        const int idx = blk - (3072 + 2880);
        pack_b_body(WO, g_wop, DMODEL, 96, idx % 96, idx / 96, tid);
    }
}

// ---------------------------------------------------------------------------
// gemm_frag (GEMM1): 128x128, BK=32, 8 warps, 3-stage cp.async.
// ---------------------------------------------------------------------------
#define GSMEM (3 * 32768)

__global__ __launch_bounds__(256)
void gemm_frag(const float* __restrict__ Ap, const float* __restrict__ Bp,
               const float* __restrict__ bias, float* __restrict__ C,
               int M, int N, int K)
{
    extern __shared__ float4 dsm[];

    const int nks  = K >> 3;
    const int nIt  = K >> 5;
    const int tid  = threadIdx.x;
    const int lane = tid & 31;
    const int wid  = tid >> 5;
    const int wm   = wid & 1;
    const int wn   = wid >> 1;
    const int g    = lane >> 2;
    const int t    = lane & 3;
    const int bN   = blockIdx.x, bM = blockIdx.y;

    const float4* Ag = (const float4*)Ap + (size_t)bM * nks * 256;
    const float4* Bg = (const float4*)Bp + (size_t)bN * nks * 256;

    float acc[4][4][4];
#pragma unroll
    for (int mt = 0; mt < 4; mt++)
#pragma unroll
        for (int nt = 0; nt < 4; nt++)
#pragma unroll
            for (int i = 0; i < 4; i++) acc[mt][nt][i] = 0.0f;

#pragma unroll
    for (int s = 0; s < 2; s++) {
        const float4* ga = Ag + (size_t)s * 1024 + tid;
        const float4* gb = Bg + (size_t)s * 1024 + tid;
        float4* sa = dsm + s * 2048 + tid;
        float4* sb = dsm + s * 2048 + 1024 + tid;
#pragma unroll
        for (int r = 0; r < 4; r++) {
            cp16(sa + 256 * r, ga + 256 * r);
            cp16(sb + 256 * r, gb + 256 * r);
        }
        asm volatile("cp.async.commit_group;" ::: "memory");
    }

    int st = 0;
    for (int it = 0; it < nIt; it++) {
        if (it + 1 < nIt) asm volatile("cp.async.wait_group 1;" ::: "memory");
        else              asm volatile("cp.async.wait_group 0;" ::: "memory");
        __syncthreads();

        if (it + 2 < nIt) {
            const int ns = (it + 2) % 3;
            const float4* ga = Ag + (size_t)(it + 2) * 1024 + tid;
            const float4* gb = Bg + (size_t)(it + 2) * 1024 + tid;
            float4* sa = dsm + ns * 2048 + tid;
            float4* sb = dsm + ns * 2048 + 1024 + tid;
#pragma unroll
            for (int r = 0; r < 4; r++) {
                cp16(sa + 256 * r, ga + 256 * r);
                cp16(sb + 256 * r, gb + 256 * r);
            }
            asm volatile("cp.async.commit_group;" ::: "memory");
        }

        const uint4* sA = (const uint4*)(dsm + st * 2048);
        const uint4* sB = (const uint4*)(dsm + st * 2048 + 1024);
#pragma unroll
        for (int ks = 0; ks < 4; ks++) {
            uint4 af[4];
            uint4 bq[2];
#pragma unroll
            for (int mt = 0; mt < 4; mt++)
                af[mt] = sA[(ks * 8 + wm * 4 + mt) * 32 + lane];
#pragma unroll
            for (int jp = 0; jp < 2; jp++)
                bq[jp] = sB[(ks * 8 + wn * 2 + jp) * 32 + lane];
            unsigned bf[4][2];
            bf[0][0] = bq[0].x; bf[0][1] = bq[0].y;
            bf[1][0] = bq[0].z; bf[1][1] = bq[0].w;
            bf[2][0] = bq[1].x; bf[2][1] = bq[1].y;
            bf[3][0] = bq[1].z; bf[3][1] = bq[1].w;
#pragma unroll
            for (int mt = 0; mt < 4; mt++)
#pragma unroll
                for (int nt = 0; nt < 4; nt++)
                    mma_tf32(acc[mt][nt], (const unsigned*)&af[mt], bf[nt]);
        }
        st = (st + 1) % 3;
    }

    const int crow0 = bM * 128, ccol0 = bN * 128;
#pragma unroll
    for (int mt = 0; mt < 4; mt++) {
        const int row = crow0 + wm * 64 + mt * 16 + g;
#pragma unroll
        for (int nt = 0; nt < 4; nt++) {
            const int col = ccol0 + wn * 32 + nt * 8 + 2 * t;
            const float2 bv = *(const float2*)&bias[col];
            float2 o0, o1;
            o0.x = acc[mt][nt][0] + bv.x;
            o0.y = acc[mt][nt][1] + bv.y;
            o1.x = acc[mt][nt][2] + bv.x;
            o1.y = acc[mt][nt][3] + bv.y;
            *(float2*)&C[(size_t)row * N + col]       = o0;
            *(float2*)&C[(size_t)(row + 8) * N + col] = o1;
        }
    }
}

// ---------------------------------------------------------------------------
// gemm_frag64 (GEMM2, round-13 proven best): 64x128 tile, 8 warps (2x4),
// warp tile 32x32, 3-stage cp.async, 24KB/stage -> 3 CTAs/SM.
// ---------------------------------------------------------------------------
#define GSMEM64 (3 * 24576)

__global__ __launch_bounds__(256)
void gemm_frag64(const float* __restrict__ Ap, const float* __restrict__ Bp,
                 const float* __restrict__ bias, float* __restrict__ C,
                 int M, int N, int K)
{
    extern __shared__ float4 dsm[];   // [3][1536] float4: A(512) then B(1024)

    const int nks  = K >> 3;
    const int nIt  = K >> 5;          // BK = 32
    const int tid  = threadIdx.x;
    const int lane = tid & 31;
    const int wid  = tid >> 5;
    const int wm   = wid & 1;
    const int wn   = wid >> 1;
    const int g    = lane >> 2;
    const int t    = lane & 3;
    const int bN   = blockIdx.x, bM = blockIdx.y;
    const int stripe = bM >> 1;
    const int half   = bM & 1;

    const float4* Ab = (const float4*)Ap + (size_t)stripe * nks * 256 + half * 128;
    const float4* Bg = (const float4*)Bp + (size_t)bN * nks * 256;

    float acc[2][4][4];
#pragma unroll
    for (int mt = 0; mt < 2; mt++)
#pragma unroll
        for (int nt = 0; nt < 4; nt++)
#pragma unroll
            for (int i = 0; i < 4; i++) acc[mt][nt][i] = 0.0f;

    const int aksl = tid >> 7;
    const int asub = tid & 127;

#pragma unroll
    for (int s = 0; s < 2; s++) {
        float4* sa = dsm + s * 1536;
        float4* sb = dsm + s * 1536 + 512;
#pragma unroll
        for (int r = 0; r < 2; r++) {
            const int idx = tid + 256 * r;
            const int kl  = aksl + 2 * r;
            cp16(sa + idx, Ab + (size_t)(s * 4 + kl) * 256 + asub);
        }
        const float4* gb = Bg + (size_t)s * 1024 + tid;
#pragma unroll
        for (int r = 0; r < 4; r++)
            cp16(sb + tid + 256 * r, gb + 256 * r);
        asm volatile("cp.async.commit_group;" ::: "memory");
    }

    int st = 0;
    for (int it = 0; it < nIt; it++) {
        if (it + 1 < nIt) asm volatile("cp.async.wait_group 1;" ::: "memory");
        else              asm volatile("cp.async.wait_group 0;" ::: "memory");
        __syncthreads();

        if (it + 2 < nIt) {
            const int ns = (it + 2) % 3;
            float4* sa = dsm + ns * 1536;
            float4* sb = dsm + ns * 1536 + 512;
#pragma unroll
            for (int r = 0; r < 2; r++) {
                const int idx = tid + 256 * r;
                const int kl  = aksl + 2 * r;
                cp16(sa + idx, Ab + (size_t)((it + 2) * 4 + kl) * 256 + asub);
            }
            const float4* gb = Bg + (size_t)(it + 2) * 1024 + tid;
#pragma unroll
            for (int r = 0; r < 4; r++)
                cp16(sb + tid + 256 * r, gb + 256 * r);
            asm volatile("cp.async.commit_group;" ::: "memory");
        }

        const uint4* sA = (const uint4*)(dsm + st * 1536);
        const uint4* sB = (const uint4*)(dsm + st * 1536 + 512);
#pragma unroll
        for (int ks = 0; ks < 4; ks++) {
            uint4 af[2];
            uint4 bq[2];
#pragma unroll
            for (int mt = 0; mt < 2; mt++)
                af[mt] = sA[(ks * 4 + wm * 2 + mt) * 32 + lane];
#pragma unroll
            for (int jp = 0; jp < 2; jp++)
                bq[jp] = sB[(ks * 8 + wn * 2 + jp) * 32 + lane];
            unsigned bf[4][2];
            bf[0][0] = bq[0].x; bf[0][1] = bq[0].y;
            bf[1][0] = bq[0].z; bf[1][1] = bq[0].w;
            bf[2][0] = bq[1].x; bf[2][1] = bq[1].y;
            bf[3][0] = bq[1].z; bf[3][1] = bq[1].w;
#pragma unroll
            for (int mt = 0; mt < 2; mt++)
#pragma unroll
                for (int nt = 0; nt < 4; nt++)
                    mma_tf32(acc[mt][nt], (const unsigned*)&af[mt], bf[nt]);
        }
        st = (st + 1) % 3;
    }

    const int crow0 = bM * 64, ccol0 = bN * 128;
#pragma unroll
    for (int mt = 0; mt < 2; mt++) {
        const int row = crow0 + wm * 32 + mt * 16 + g;
#pragma unroll
        for (int nt = 0; nt < 4; nt++) {
            const int col = ccol0 + wn * 32 + nt * 8 + 2 * t;
            const float2 bv = *(const float2*)&bias[col];
            float2 o0, o1;
            o0.x = acc[mt][nt][0] + bv.x;
            o0.y = acc[mt][nt][1] + bv.y;
            o1.x = acc[mt][nt][2] + bv.x;
            o1.y = acc[mt][nt][3] + bv.y;
            *(float2*)&C[(size_t)row * N + col]       = o0;
            *(float2*)&C[(size_t)(row + 8) * N + col] = o1;
        }
    }
}

// ---------------------------------------------------------------------------
// Local trittention (round-14): 2 windows/block, frag-packed a/b in smem,
// mma scores + mma Z epilogue; z scatter-stored in A-frag layout (tf32).
// ---------------------------------------------------------------------------
#define SPAD 68
#define MPAD 36
#define FRAG_WORDS (3 * 8 * 132)   // 3168
#define ASMEM ((2 * FRAG_WORDS + 2 * 48 * SPAD + 32 * SPAD + 2 * 2 * 16 * MPAD + 48) * 4)

__device__ __forceinline__ void store_zp(float v, int row, int col) {
    const int stripe = row >> 7;
    const int ii     = (row >> 4) & 7;
    const int gg     = row & 15;
    const int gq     = gg & 7;
    const int hir    = gg >> 3;
    const int ks     = col >> 3;
    const int cc     = col & 7;
    const int tc     = cc & 3;
    const int hic    = cc >> 2;
    const size_t qi = ((size_t)(stripe * 96 + ks) * 8 + ii) * 32 + (gq * 4 + tc);
    g_zp[qi * 4 + (hir + 2 * hic)] = __uint_as_float(f2tf32(v));
}

__global__ __launch_bounds__(512, 2)
void attn_kernel()
{
    extern __shared__ float smf[];
    float*    saf  = smf;                          // [3*8*132] a frags (fp32)
    unsigned* sbq  = (unsigned*)(saf + FRAG_WORDS);// [3*8*132] b frags (tf32)
    float*    sd   = (float*)(sbq + FRAG_WORDS);   // [48][SPAD]
    float*    se   = sd + 48 * SPAD;
    float*    sc   = se + 48 * SPAD;               // [32][SPAD]
    float*    spm  = sc + 32 * SPAD;               // [2][16][MPAD]
    float*    spl  = spm + 2 * 16 * MPAD;
    int*      sbbt = (int*)(spl + 2 * 16 * MPAD);  // [48]

    const int blk = blockIdx.x;
    const int p   = blk & 63;
    const int bh  = blk >> 6;
    const int b   = bh / NH;
    const int h   = bh % NH;
    const int tid = threadIdx.x;
    const int t0  = (2 * p - 1) * WIN;

    for (int idx = tid; idx < 48 * 16; idx += 512) {
        const int r   = idx >> 4;
        const int c4  = (idx & 15) << 2;
        const int tok = t0 + r;
        float4 z4 = make_float4(0.f, 0.f, 0.f, 0.f);
        float4 va = z4, vb = z4, vd = z4, ve = z4;
        if (tok >= 0) {
            const float* base = g_abcde + ((size_t)(b * TT + tok)) * (5 * DMODEL)
                              + h * DH + c4;
            va = *(const float4*)(base + 0 * DMODEL);
            vb = *(const float4*)(base + 1 * DMODEL);
            vd = *(const float4*)(base + 3 * DMODEL);
            ve = *(const float4*)(base + 4 * DMODEL);
        }
        *(float4*)&sd[r * SPAD + c4] = vd;
        *(float4*)&se[r * SPAD + c4] = ve;

        const int G    = r >> 4;
        const int rr   = r & 15;
        const int gg   = rr & 7;
        const int hi   = rr >> 3;
        const int ks   = c4 >> 3;
        const int tsel = (c4 & 7) >> 2;
        const int abase = (G * 8 + ks) * 132 + gg * 16 + (hi + 2 * tsel);
        saf[abase + 0]  = va.x;
        saf[abase + 4]  = va.y;
        saf[abase + 8]  = va.z;
        saf[abase + 12] = va.w;
        const int bbase = (G * 8 + ks) * 132 + gg * 16 + (2 * hi + tsel);
        sbq[bbase + 0]  = f2tf32(vb.x);
        sbq[bbase + 4]  = f2tf32(vb.y);
        sbq[bbase + 8]  = f2tf32(vb.z);
        sbq[bbase + 12] = f2tf32(vb.w);
    }
    {
        const int r   = tid >> 4;
        const int c4  = (tid & 15) << 2;
        const int tok = t0 + 16 + r;
        const float* base = g_abcde + ((size_t)(b * TT + tok)) * (5 * DMODEL)
                          + 2 * DMODEL + h * DH + c4;
        *(float4*)&sc[r * SPAD + c4] = *(const float4*)base;
    }
    if (tid < 48) sbbt[tid] = (t0 + tid > 0) ? (t0 + tid) : 0;
    __syncthreads();

    const int q    = tid >> 5;
    const int lane = tid & 31;
    const int g    = lane >> 2;
    const int t    = lane & 3;

#pragma unroll 1
    for (int w = 0; w < 2; w++) {
        const int ro = 16 * w;
        const int qg = t0 + 16 + ro + q;

        float acc[2][4][4];
#pragma unroll
        for (int mt = 0; mt < 2; mt++)
#pragma unroll
            for (int nt = 0; nt < 4; nt++)
#pragma unroll
                for (int i = 0; i < 4; i++) acc[mt][nt][i] = 0.0f;

#pragma unroll
        for (int ks = 0; ks < 8; ks++) {
            const int k0 = ks * 8;
            const float c0 = sc[(ro + q) * SPAD + k0 + t];
            const float c1 = sc[(ro + q) * SPAD + k0 + t + 4];
            unsigned af[2][4];
#pragma unroll
            for (int mt = 0; mt < 2; mt++) {
                const float4 a4 = *(const float4*)&saf[((w + mt) * 8 + ks) * 132 + lane * 4];
                af[mt][0] = f2tf32(a4.x * c0);
                af[mt][1] = f2tf32(a4.y * c0);
                af[mt][2] = f2tf32(a4.z * c1);
                af[mt][3] = f2tf32(a4.w * c1);
            }
#pragma unroll
            for (int jp = 0; jp < 2; jp++) {
                const uint4 bq = *(const uint4*)&sbq[((w + jp) * 8 + ks) * 132 + lane * 4];
                unsigned bf0[2] = {bq.x, bq.y};
                unsigned bf1[2] = {bq.z, bq.w};
#pragma unroll
                for (int mt = 0; mt < 2; mt++) {
                    mma_tf32(acc[mt][2 * jp],     af[mt], bf0);
                    mma_tf32(acc[mt][2 * jp + 1], af[mt], bf1);
                }
            }
        }

        // mask + scale
#pragma unroll
        for (int mt = 0; mt < 2; mt++)
#pragma unroll
            for (int nt = 0; nt < 4; nt++)
#pragma unroll
                for (int i = 0; i < 4; i++) {
                    const int bm = sbbt[ro + mt * 16 + g + ((i < 2) ? 0 : 8)];
                    const int bl = sbbt[ro + nt * 8 + 2 * t + (i & 1)];
                    float s = acc[mt][nt][i];
                    if ((qg < bl) || (bl <= bm) || (s == 0.0f)) s = IGNORE_V;
                    acc[mt][nt][i] = s * (1.0f / 64.0f);
                }

        // softmax
        float mx = acc[0][0][0];
#pragma unroll
        for (int mt = 0; mt < 2; mt++)
#pragma unroll
            for (int nt = 0; nt < 4; nt++)
#pragma unroll
                for (int i = 0; i < 4; i++) mx = fmaxf(mx, acc[mt][nt][i]);
#pragma unroll
        for (int off = 16; off; off >>= 1)
            mx = fmaxf(mx, __shfl_xor_sync(0xffffffffu, mx, off));

        float sum = 0.0f;
#pragma unroll
        for (int mt = 0; mt < 2; mt++)
#pragma unroll
            for (int nt = 0; nt < 4; nt++)
#pragma unroll
                for (int i = 0; i < 4; i++) {
                    float e = __expf(acc[mt][nt][i] - mx);
                    acc[mt][nt][i] = e;
                    sum += e;
                }
#pragma unroll
        for (int off = 16; off; off >>= 1)
            sum += __shfl_xor_sync(0xffffffffu, sum, off);
        const float inv = 1.0f / sum;

        // marginals
        float rA[2], rB[2];
#pragma unroll
        for (int mt = 0; mt < 2; mt++) {
            float a0 = 0.f, b0 = 0.f;
#pragma unroll
            for (int nt = 0; nt < 4; nt++) {
                a0 += acc[mt][nt][0] + acc[mt][nt][1];
                b0 += acc[mt][nt][2] + acc[mt][nt][3];
            }
#pragma unroll
            for (int off = 1; off <= 2; off <<= 1) {
                a0 += __shfl_xor_sync(0xffffffffu, a0, off);
                b0 += __shfl_xor_sync(0xffffffffu, b0, off);
            }
            rA[mt] = a0; rB[mt] = b0;
        }
        float cs[4][2];
#pragma unroll
        for (int nt = 0; nt < 4; nt++)
#pragma unroll
            for (int j = 0; j < 2; j++) {
                float v = acc[0][nt][j] + acc[0][nt][j + 2]
                        + acc[1][nt][j] + acc[1][nt][j + 2];
#pragma unroll
                for (int off = 4; off <= 16; off <<= 1)
                    v += __shfl_xor_sync(0xffffffffu, v, off);
                cs[nt][j] = v;
            }

        float* pm = spm + (w * 16 + q) * MPAD;
        float* pl = spl + (w * 16 + q) * MPAD;
        if (t == 0) {
            pm[g]      = rA[0] * inv;
            pm[g + 8]  = rB[0] * inv;
            pm[g + 16] = rA[1] * inv;
            pm[g + 24] = rB[1] * inv;
        }
        if (g == 0) {
#pragma unroll
            for (int nt = 0; nt < 4; nt++) {
                pl[nt * 8 + 2 * t]     = cs[nt][0] * inv;
                pl[nt * 8 + 2 * t + 1] = cs[nt][1] * inv;
            }
        }
    }
    __syncthreads();

    // epilogue: all 16 warps; w = q>>3, nt = q&7
    {
        const int w  = q >> 3;
        const int nt = q & 7;
        const int ro = 16 * w;
        float zacc[4] = {0.f, 0.f, 0.f, 0.f};
#pragma unroll
        for (int term = 0; term < 2; term++) {
            const float* P = (term ? spl : spm) + (w * 16) * MPAD;
            const float* V = (term ? se : sd) + ro * SPAD;
#pragma unroll
            for (int ks = 0; ks < 4; ks++) {
                const int k0 = ks * 8;
                unsigned af[4], bf[2];
                af[0] = f2tf32(P[g * MPAD + k0 + t]);
                af[1] = f2tf32(P[(g + 8) * MPAD + k0 + t]);
                af[2] = f2tf32(P[g * MPAD + k0 + t + 4]);
                af[3] = f2tf32(P[(g + 8) * MPAD + k0 + t + 4]);
                bf[0] = f2tf32(V[(k0 + t) * SPAD + nt * 8 + g]);
                bf[1] = f2tf32(V[(k0 + t + 4) * SPAD + nt * 8 + g]);
                mma_tf32(zacc, af, bf);
            }
        }
        const int row0 = b * TT + (2 * p + w) * WIN + g;
        const int col0 = h * DH + nt * 8 + 2 * t;
        store_zp(zacc[0], row0,     col0);
        store_zp(zacc[1], row0,     col0 + 1);
        store_zp(zacc[2], row0 + 8, col0);
        store_zp(zacc[3], row0 + 8, col0 + 1);
    }
}

// ---------------------------------------------------------------------------
extern "C" void kernel_launch(void* const* d_in, const int* in_sizes, int n_in,
                              void* d_out, int out_size)
{
    const float* x  = (const float*)d_in[0];  // (2,2048,768)
    const float* W1 = (const float*)d_in[1];  // (768, 3840)
    const float* b1 = (const float*)d_in[2];  // (3840)
    const float* WO = (const float*)d_in[3];  // (768, 768)
    const float* bO = (const float*)d_in[4];  // (768)
    float* out = (float*)d_out;               // (2,2048,768)

    float *abcde, *xp, *zp, *w1p, *wop;
    cudaGetSymbolAddress((void**)&abcde, g_abcde);
    cudaGetSymbolAddress((void**)&xp,    g_xp);
    cudaGetSymbolAddress((void**)&zp,    g_zp);
    cudaGetSymbolAddress((void**)&w1p,   g_w1p);
    cudaGetSymbolAddress((void**)&wop,   g_wop);

    cudaFuncSetAttribute(gemm_frag,
                         cudaFuncAttributeMaxDynamicSharedMemorySize, GSMEM);
    cudaFuncSetAttribute(gemm_frag64,
                         cudaFuncAttributeMaxDynamicSharedMemorySize, GSMEM64);
    cudaFuncSetAttribute(attn_kernel,
                         cudaFuncAttributeMaxDynamicSharedMemorySize, ASMEM);

    const int M  = BB * TT;          // 4096
    const int N1 = 5 * NH * DH;      // 3840
    const int N2 = DMODEL;           // 768
    const int K  = DMODEL;           // 768

    // 0) all operand packing in one launch
    pack_all<<<3072 + 2880 + 576, 256>>>(x, W1, WO);

    // 1) abcde = x @ W1 + b1
    gemm_frag<<<dim3(N1 / 128, M / 128), 256, GSMEM>>>(xp, w1p, b1, abcde, M, N1, K);

    // 2) local trittention (2 windows/block) -> zp (packed, tf32)
    attn_kernel<<<BB * NH * (NWIN / 2), 512, ASMEM>>>();

    // 3) out = z @ WO + bO  (64-row tiles: 384 blocks, 3 CTAs/SM)
    gemm_frag64<<<dim3(N2 / 128, M / 64), 256, GSMEM64>>>(zp, wop, bO, out, M, N2, K);
}

// round 17
// speedup vs baseline: 1.3794x; 1.3794x over previous
#include <cuda_runtime.h>
#include <cuda_fp16.h>
#include <cstdint>

#define DMODEL 768
#define NH     12
#define DH     64
#define WIN    16
#define NWIN   128
#define BB     2
#define TT     2048
#define IGNORE_V (-1.0e6f)

// Scratch (device globals: allocation-free). Packed operand arrays hold fp16
// data (reinterpreted); sizes are generous.
__device__ float g_abcde[(size_t)BB * TT * 5 * NH * DH]; // 62.9 MB fp32
__device__ float g_xp[(size_t)BB * TT * DMODEL];         // x packed (fp16 A-frag)
__device__ float g_zp[(size_t)BB * TT * DMODEL];         // z packed (fp16 A-frag)
__device__ float g_w1p[(size_t)DMODEL * 5 * NH * DH];    // W1 packed (fp16 B-pair)
__device__ float g_wop[(size_t)DMODEL * DMODEL];         // WO packed (fp16 B-pair)

// ---------------------------------------------------------------------------
__device__ __forceinline__ unsigned f2tf32(float x) {
    unsigned r;
    asm("cvt.rna.tf32.f32 %0, %1;" : "=r"(r) : "f"(x));
    return r;
}
__device__ __forceinline__ unsigned smem_u32(const void* p) {
    unsigned a;
    asm("{ .reg .u64 t; cvta.to.shared.u64 t, %1; cvt.u32.u64 %0, t; }" : "=r"(a) : "l"(p));
    return a;
}
__device__ __forceinline__ void cp16(void* s, const void* g) {
    asm volatile("cp.async.cg.shared.global [%0], [%1], 16;"
                 :: "r"(smem_u32(s)), "l"(g) : "memory");
}
__device__ __forceinline__ void mma_tf32(float c[4], const unsigned a[4], const unsigned b[2]) {
    asm volatile(
        "mma.sync.aligned.m16n8k8.row.col.f32.tf32.tf32.f32 "
        "{%0,%1,%2,%3}, {%4,%5,%6,%7}, {%8,%9}, {%0,%1,%2,%3};"
        : "+f"(c[0]), "+f"(c[1]), "+f"(c[2]), "+f"(c[3])
        : "r"(a[0]), "r"(a[1]), "r"(a[2]), "r"(a[3]), "r"(b[0]), "r"(b[1]));
}
__device__ __forceinline__ void mma_h(float c[4], const unsigned a[4], const unsigned b[2]) {
    asm volatile(
        "mma.sync.aligned.m16n8k16.row.col.f32.f16.f16.f32 "
        "{%0,%1,%2,%3}, {%4,%5,%6,%7}, {%8,%9}, {%0,%1,%2,%3};"
        : "+f"(c[0]), "+f"(c[1]), "+f"(c[2]), "+f"(c[3])
        : "r"(a[0]), "r"(a[1]), "r"(a[2]), "r"(a[3]), "r"(b[0]), "r"(b[1]));
}
__device__ __forceinline__ unsigned h2u(__half2 h) { return *(unsigned*)&h; }

// ---------------------------------------------------------------------------
// fp16 pack bodies. nks16 = K/16 kslices.
// A-frag quad (16B = 8 halves) at ((stripe*nks+ks)*8+i)*32+lane:
//   {A[g][2t],A[g][2t+1], A[g+8][2t],A[g+8][2t+1],
//    A[g][2t+8],A[g][2t+9], A[g+8][2t+8],A[g+8][2t+9]}  (rows rel. to i*16)
// B-pair quad at ((cb*nks+ks)*8+jp)*32+lane: frags for n0 and n0+8:
//   {B[2t][n0],B[2t+1][n0], B[2t+8][n0],B[2t+9][n0],  (same for n0+8)}
// ---------------------------------------------------------------------------
__device__ __forceinline__ void pack_a_h(const float* __restrict__ in,
                                         float* __restrict__ out,
                                         int K, int nks, int ks, int stripe, int tid)
{
    const int i = tid >> 5, lane = tid & 31;
    const int g = lane >> 2, t = lane & 3;
    const int row = stripe * 128 + i * 16 + g;
    const float* p = in + (size_t)row * K + ks * 16 + 2 * t;
    const float2 r0c0 = *(const float2*)(p);
    const float2 r1c0 = *(const float2*)(p + (size_t)8 * K);
    const float2 r0c8 = *(const float2*)(p + 8);
    const float2 r1c8 = *(const float2*)(p + (size_t)8 * K + 8);
    uint4 o;
    o.x = h2u(__floats2half2_rn(r0c0.x, r0c0.y));
    o.y = h2u(__floats2half2_rn(r1c0.x, r1c0.y));
    o.z = h2u(__floats2half2_rn(r0c8.x, r0c8.y));
    o.w = h2u(__floats2half2_rn(r1c8.x, r1c8.y));
    ((uint4*)out)[((size_t)(stripe * nks + ks) * 8 + i) * 32 + lane] = o;
}

__device__ __forceinline__ void pack_b_h(const float* __restrict__ in,
                                         float* __restrict__ out,
                                         int N, int nks, int ks, int cb, int tid)
{
    const int jp = tid >> 5, lane = tid & 31;
    const int g = lane >> 2, t = lane & 3;
    const int k0 = ks * 16 + 2 * t;
    const int n0 = cb * 128 + jp * 16 + g;
    const float b0 = in[(size_t)(k0 + 0) * N + n0];
    const float b1 = in[(size_t)(k0 + 1) * N + n0];
    const float b2 = in[(size_t)(k0 + 8) * N + n0];
    const float b3 = in[(size_t)(k0 + 9) * N + n0];
    const float c0 = in[(size_t)(k0 + 0) * N + n0 + 8];
    const float c1 = in[(size_t)(k0 + 1) * N + n0 + 8];
    const float c2 = in[(size_t)(k0 + 8) * N + n0 + 8];
    const float c3 = in[(size_t)(k0 + 9) * N + n0 + 8];
    uint4 o;
    o.x = h2u(__floats2half2_rn(b0, b1));
    o.y = h2u(__floats2half2_rn(b2, b3));
    o.z = h2u(__floats2half2_rn(c0, c1));
    o.w = h2u(__floats2half2_rn(c2, c3));
    ((uint4*)out)[((size_t)(cb * nks + ks) * 8 + jp) * 32 + lane] = o;
}

// fused: x (48*32=1536), W1 (48*30=1440), WO (48*6=288) => 3264 blocks
__global__ __launch_bounds__(256)
void pack_all(const float* __restrict__ x, const float* __restrict__ W1,
              const float* __restrict__ WO)
{
    const int blk = blockIdx.x;
    const int tid = threadIdx.x;
    if (blk < 1536) {
        pack_a_h(x, g_xp, DMODEL, 48, blk % 48, blk / 48, tid);
    } else if (blk < 1536 + 1440) {
        const int idx = blk - 1536;
        pack_b_h(W1, g_w1p, 5 * NH * DH, 48, idx % 48, idx / 48, tid);
    } else {
        const int idx = blk - (1536 + 1440);
        pack_b_h(WO, g_wop, DMODEL, 48, idx % 48, idx / 48, tid);
    }
}

// ---------------------------------------------------------------------------
// gemm_h (GEMM1): fp16 m16n8k16. Block 128x128, BK=32 (2 kslices16),
// 8 warps (2x4), warp tile 64x32, 3-stage cp.async (16KB/stage = 48KB).
// ---------------------------------------------------------------------------
#define GSMEM (3 * 16384)

__global__ __launch_bounds__(256)
void gemm_h(const float* __restrict__ Ap, const float* __restrict__ Bp,
            const float* __restrict__ bias, float* __restrict__ C,
            int M, int N, int K)
{
    extern __shared__ uint4 dsm[];   // [3][1024]: A(512) then B(512)

    const int nks  = K >> 4;          // 48
    const int nIt  = K >> 5;          // 24
    const int tid  = threadIdx.x;
    const int lane = tid & 31;
    const int wid  = tid >> 5;
    const int wm   = wid & 1;
    const int wn   = wid >> 1;
    const int g    = lane >> 2;
    const int t    = lane & 3;
    const int bN   = blockIdx.x, bM = blockIdx.y;

    const uint4* Ag = (const uint4*)Ap + (size_t)bM * nks * 256;
    const uint4* Bg = (const uint4*)Bp + (size_t)bN * nks * 256;

    float acc[4][4][4];
#pragma unroll
    for (int mt = 0; mt < 4; mt++)
#pragma unroll
        for (int nt = 0; nt < 4; nt++)
#pragma unroll
            for (int i = 0; i < 4; i++) acc[mt][nt][i] = 0.0f;

#pragma unroll
    for (int s = 0; s < 2; s++) {
        uint4* sa = dsm + s * 1024;
        uint4* sb = sa + 512;
#pragma unroll
        for (int r = 0; r < 2; r++) {
            cp16(sa + tid + 256 * r, Ag + (size_t)s * 512 + tid + 256 * r);
            cp16(sb + tid + 256 * r, Bg + (size_t)s * 512 + tid + 256 * r);
        }
        asm volatile("cp.async.commit_group;" ::: "memory");
    }

    int st = 0;
    for (int it = 0; it < nIt; it++) {
        if (it + 1 < nIt) asm volatile("cp.async.wait_group 1;" ::: "memory");
        else              asm volatile("cp.async.wait_group 0;" ::: "memory");
        __syncthreads();

        if (it + 2 < nIt) {
            const int ns = (it + 2) % 3;
            uint4* sa = dsm + ns * 1024;
            uint4* sb = sa + 512;
#pragma unroll
            for (int r = 0; r < 2; r++) {
                cp16(sa + tid + 256 * r, Ag + (size_t)(it + 2) * 512 + tid + 256 * r);
                cp16(sb + tid + 256 * r, Bg + (size_t)(it + 2) * 512 + tid + 256 * r);
            }
            asm volatile("cp.async.commit_group;" ::: "memory");
        }

        const uint4* sA = dsm + st * 1024;
        const uint4* sB = sA + 512;
#pragma unroll
        for (int ks = 0; ks < 2; ks++) {
            uint4 af[4];
            uint4 bq[2];
#pragma unroll
            for (int mt = 0; mt < 4; mt++)
                af[mt] = sA[(ks * 8 + wm * 4 + mt) * 32 + lane];
#pragma unroll
            for (int jp = 0; jp < 2; jp++)
                bq[jp] = sB[(ks * 8 + wn * 2 + jp) * 32 + lane];
            unsigned bf[4][2];
            bf[0][0] = bq[0].x; bf[0][1] = bq[0].y;
            bf[1][0] = bq[0].z; bf[1][1] = bq[0].w;
            bf[2][0] = bq[1].x; bf[2][1] = bq[1].y;
            bf[3][0] = bq[1].z; bf[3][1] = bq[1].w;
#pragma unroll
            for (int mt = 0; mt < 4; mt++)
#pragma unroll
                for (int nt = 0; nt < 4; nt++)
                    mma_h(acc[mt][nt], (const unsigned*)&af[mt], bf[nt]);
        }
        st = (st + 1) % 3;
    }

    const int crow0 = bM * 128, ccol0 = bN * 128;
#pragma unroll
    for (int mt = 0; mt < 4; mt++) {
        const int row = crow0 + wm * 64 + mt * 16 + g;
#pragma unroll
        for (int nt = 0; nt < 4; nt++) {
            const int col = ccol0 + wn * 32 + nt * 8 + 2 * t;
            const float2 bv = *(const float2*)&bias[col];
            float2 o0, o1;
            o0.x = acc[mt][nt][0] + bv.x;
            o0.y = acc[mt][nt][1] + bv.y;
            o1.x = acc[mt][nt][2] + bv.x;
            o1.y = acc[mt][nt][3] + bv.y;
            *(float2*)&C[(size_t)row * N + col]       = o0;
            *(float2*)&C[(size_t)(row + 8) * N + col] = o1;
        }
    }
}

// ---------------------------------------------------------------------------
// gemm_h64 (GEMM2): fp16, 64x128 tile, 8 warps (2x4), warp tile 32x32,
// 3-stage cp.async (12KB/stage = 36KB).
// ---------------------------------------------------------------------------
#define GSMEM64 (3 * 12288)

__global__ __launch_bounds__(256)
void gemm_h64(const float* __restrict__ Ap, const float* __restrict__ Bp,
              const float* __restrict__ bias, float* __restrict__ C,
              int M, int N, int K)
{
    extern __shared__ uint4 dsm[];   // [3][768]: A(256) then B(512)

    const int nks  = K >> 4;          // 48
    const int nIt  = K >> 5;          // 24
    const int tid  = threadIdx.x;
    const int lane = tid & 31;
    const int wid  = tid >> 5;
    const int wm   = wid & 1;
    const int wn   = wid >> 1;
    const int g    = lane >> 2;
    const int t    = lane & 3;
    const int bN   = blockIdx.x, bM = blockIdx.y;
    const int stripe = bM >> 1;
    const int half   = bM & 1;

    const uint4* Ag = (const uint4*)Ap + (size_t)stripe * nks * 256;
    const uint4* Bg = (const uint4*)Bp + (size_t)bN * nks * 256;

    float acc[2][4][4];
#pragma unroll
    for (int mt = 0; mt < 2; mt++)
#pragma unroll
        for (int nt = 0; nt < 4; nt++)
#pragma unroll
            for (int i = 0; i < 4; i++) acc[mt][nt][i] = 0.0f;

    // A staging decomposition: tid = ks*128 + i4*32 + l
    const int aks = tid >> 7;
    const int ai4 = (tid >> 5) & 3;
    const int al  = tid & 31;

#pragma unroll
    for (int s = 0; s < 2; s++) {
        uint4* sa = dsm + s * 768;
        uint4* sb = sa + 256;
        cp16(sa + tid, Ag + (size_t)(s * 2 + aks) * 256 + (half * 4 + ai4) * 32 + al);
#pragma unroll
        for (int r = 0; r < 2; r++)
            cp16(sb + tid + 256 * r, Bg + (size_t)s * 512 + tid + 256 * r);
        asm volatile("cp.async.commit_group;" ::: "memory");
    }

    int st = 0;
    for (int it = 0; it < nIt; it++) {
        if (it + 1 < nIt) asm volatile("cp.async.wait_group 1;" ::: "memory");
        else              asm volatile("cp.async.wait_group 0;" ::: "memory");
        __syncthreads();

        if (it + 2 < nIt) {
            const int ns = (it + 2) % 3;
            uint4* sa = dsm + ns * 768;
            uint4* sb = sa + 256;
            cp16(sa + tid, Ag + (size_t)((it + 2) * 2 + aks) * 256 + (half * 4 + ai4) * 32 + al);
#pragma unroll
            for (int r = 0; r < 2; r++)
                cp16(sb + tid + 256 * r, Bg + (size_t)(it + 2) * 512 + tid + 256 * r);
            asm volatile("cp.async.commit_group;" ::: "memory");
        }

        const uint4* sA = dsm + st * 768;
        const uint4* sB = sA + 256;
#pragma unroll
        for (int ks = 0; ks < 2; ks++) {
            uint4 af[2];
            uint4 bq[2];
#pragma unroll
            for (int mt = 0; mt < 2; mt++)
                af[mt] = sA[(ks * 4 + wm * 2 + mt) * 32 + lane];
#pragma unroll
            for (int jp = 0; jp < 2; jp++)
                bq[jp] = sB[(ks * 8 + wn * 2 + jp) * 32 + lane];
            unsigned bf[4][2];
            bf[0][0] = bq[0].x; bf[0][1] = bq[0].y;
            bf[1][0] = bq[0].z; bf[1][1] = bq[0].w;
            bf[2][0] = bq[1].x; bf[2][1] = bq[1].y;
            bf[3][0] = bq[1].z; bf[3][1] = bq[1].w;
#pragma unroll
            for (int mt = 0; mt < 2; mt++)
#pragma unroll
                for (int nt = 0; nt < 4; nt++)
                    mma_h(acc[mt][nt], (const unsigned*)&af[mt], bf[nt]);
        }
        st = (st + 1) % 3;
    }

    const int crow0 = bM * 64, ccol0 = bN * 128;
#pragma unroll
    for (int mt = 0; mt < 2; mt++) {
        const int row = crow0 + wm * 32 + mt * 16 + g;
#pragma unroll
        for (int nt = 0; nt < 4; nt++) {
            const int col = ccol0 + wn * 32 + nt * 8 + 2 * t;
            const float2 bv = *(const float2*)&bias[col];
            float2 o0, o1;
            o0.x = acc[mt][nt][0] + bv.x;
            o0.y = acc[mt][nt][1] + bv.y;
            o1.x = acc[mt][nt][2] + bv.x;
            o1.y = acc[mt][nt][3] + bv.y;
            *(float2*)&C[(size_t)row * N + col]       = o0;
            *(float2*)&C[(size_t)(row + 8) * N + col] = o1;
        }
    }
}

// ---------------------------------------------------------------------------
// Local trittention (round-14 proven): 2 windows/block, frag-packed a/b,
// tf32 mma scores + mma Z epilogue. z is stored in the fp16 A-frag layout.
// ---------------------------------------------------------------------------
#define SPAD 68
#define MPAD 36
#define FRAG_WORDS (3 * 8 * 132)
#define ASMEM ((2 * FRAG_WORDS + 2 * 48 * SPAD + 32 * SPAD + 2 * 2 * 16 * MPAD + 48) * 4)

__global__ __launch_bounds__(512, 2)
void attn_kernel()
{
    extern __shared__ float smf[];
    float*    saf  = smf;                          // a frags (fp32)
    unsigned* sbq  = (unsigned*)(saf + FRAG_WORDS);// b frags (tf32)
    float*    sd   = (float*)(sbq + FRAG_WORDS);   // [48][SPAD]
    float*    se   = sd + 48 * SPAD;
    float*    sc   = se + 48 * SPAD;               // [32][SPAD]
    float*    spm  = sc + 32 * SPAD;               // [2][16][MPAD]
    float*    spl  = spm + 2 * 16 * MPAD;
    int*      sbbt = (int*)(spl + 2 * 16 * MPAD);  // [48]

    const int blk = blockIdx.x;
    const int p   = blk & 63;
    const int bh  = blk >> 6;
    const int b   = bh / NH;
    const int h   = bh % NH;
    const int tid = threadIdx.x;
    const int t0  = (2 * p - 1) * WIN;

    for (int idx = tid; idx < 48 * 16; idx += 512) {
        const int r   = idx >> 4;
        const int c4  = (idx & 15) << 2;
        const int tok = t0 + r;
        float4 z4 = make_float4(0.f, 0.f, 0.f, 0.f);
        float4 va = z4, vb = z4, vd = z4, ve = z4;
        if (tok >= 0) {
            const float* base = g_abcde + ((size_t)(b * TT + tok)) * (5 * DMODEL)
                              + h * DH + c4;
            va = *(const float4*)(base + 0 * DMODEL);
            vb = *(const float4*)(base + 1 * DMODEL);
            vd = *(const float4*)(base + 3 * DMODEL);
            ve = *(const float4*)(base + 4 * DMODEL);
        }
        *(float4*)&sd[r * SPAD + c4] = vd;
        *(float4*)&se[r * SPAD + c4] = ve;

        const int G    = r >> 4;
        const int rr   = r & 15;
        const int gg   = rr & 7;
        const int hi   = rr >> 3;
        const int ks   = c4 >> 3;
        const int tsel = (c4 & 7) >> 2;
        const int abase = (G * 8 + ks) * 132 + gg * 16 + (hi + 2 * tsel);
        saf[abase + 0]  = va.x;
        saf[abase + 4]  = va.y;
        saf[abase + 8]  = va.z;
        saf[abase + 12] = va.w;
        const int bbase = (G * 8 + ks) * 132 + gg * 16 + (2 * hi + tsel);
        sbq[bbase + 0]  = f2tf32(vb.x);
        sbq[bbase + 4]  = f2tf32(vb.y);
        sbq[bbase + 8]  = f2tf32(vb.z);
        sbq[bbase + 12] = f2tf32(vb.w);
    }
    {
        const int r   = tid >> 4;
        const int c4  = (tid & 15) << 2;
        const int tok = t0 + 16 + r;
        const float* base = g_abcde + ((size_t)(b * TT + tok)) * (5 * DMODEL)
                          + 2 * DMODEL + h * DH + c4;
        *(float4*)&sc[r * SPAD + c4] = *(const float4*)base;
    }
    if (tid < 48) sbbt[tid] = (t0 + tid > 0) ? (t0 + tid) : 0;
    __syncthreads();

    const int q    = tid >> 5;
    const int lane = tid & 31;
    const int g    = lane >> 2;
    const int t    = lane & 3;

#pragma unroll 1
    for (int w = 0; w < 2; w++) {
        const int ro = 16 * w;
        const int qg = t0 + 16 + ro + q;

        float acc[2][4][4];
#pragma unroll
        for (int mt = 0; mt < 2; mt++)
#pragma unroll
            for (int nt = 0; nt < 4; nt++)
#pragma unroll
                for (int i = 0; i < 4; i++) acc[mt][nt][i] = 0.0f;

#pragma unroll
        for (int ks = 0; ks < 8; ks++) {
            const int k0 = ks * 8;
            const float c0 = sc[(ro + q) * SPAD + k0 + t];
            const float c1 = sc[(ro + q) * SPAD + k0 + t + 4];
            unsigned af[2][4];
#pragma unroll
            for (int mt = 0; mt < 2; mt++) {
                const float4 a4 = *(const float4*)&saf[((w + mt) * 8 + ks) * 132 + lane * 4];
                af[mt][0] = f2tf32(a4.x * c0);
                af[mt][1] = f2tf32(a4.y * c0);
                af[mt][2] = f2tf32(a4.z * c1);
                af[mt][3] = f2tf32(a4.w * c1);
            }
#pragma unroll
            for (int jp = 0; jp < 2; jp++) {
                const uint4 bq = *(const uint4*)&sbq[((w + jp) * 8 + ks) * 132 + lane * 4];
                unsigned bf0[2] = {bq.x, bq.y};
                unsigned bf1[2] = {bq.z, bq.w};
#pragma unroll
                for (int mt = 0; mt < 2; mt++) {
                    mma_tf32(acc[mt][2 * jp],     af[mt], bf0);
                    mma_tf32(acc[mt][2 * jp + 1], af[mt], bf1);
                }
            }
        }

        // mask + scale
#pragma unroll
        for (int mt = 0; mt < 2; mt++)
#pragma unroll
            for (int nt = 0; nt < 4; nt++)
#pragma unroll
                for (int i = 0; i < 4; i++) {
                    const int bm = sbbt[ro + mt * 16 + g + ((i < 2) ? 0 : 8)];
                    const int bl = sbbt[ro + nt * 8 + 2 * t + (i & 1)];
                    float s = acc[mt][nt][i];
                    if ((qg < bl) || (bl <= bm) || (s == 0.0f)) s = IGNORE_V;
                    acc[mt][nt][i] = s * (1.0f / 64.0f);
                }

        // softmax
        float mx = acc[0][0][0];
#pragma unroll
        for (int mt = 0; mt < 2; mt++)
#pragma unroll
            for (int nt = 0; nt < 4; nt++)
#pragma unroll
                for (int i = 0; i < 4; i++) mx = fmaxf(mx, acc[mt][nt][i]);
#pragma unroll
        for (int off = 16; off; off >>= 1)
            mx = fmaxf(mx, __shfl_xor_sync(0xffffffffu, mx, off));

        float sum = 0.0f;
#pragma unroll
        for (int mt = 0; mt < 2; mt++)
#pragma unroll
            for (int nt = 0; nt < 4; nt++)
#pragma unroll
                for (int i = 0; i < 4; i++) {
                    float e = __expf(acc[mt][nt][i] - mx);
                    acc[mt][nt][i] = e;
                    sum += e;
                }
#pragma unroll
        for (int off = 16; off; off >>= 1)
            sum += __shfl_xor_sync(0xffffffffu, sum, off);
        const float inv = 1.0f / sum;

        // marginals
        float rA[2], rB[2];
#pragma unroll
        for (int mt = 0; mt < 2; mt++) {
            float a0 = 0.f, b0 = 0.f;
#pragma unroll
            for (int nt = 0; nt < 4; nt++) {
                a0 += acc[mt][nt][0] + acc[mt][nt][1];
                b0 += acc[mt][nt][2] + acc[mt][nt][3];
            }
#pragma unroll
            for (int off = 1; off <= 2; off <<= 1) {
                a0 += __shfl_xor_sync(0xffffffffu, a0, off);
                b0 += __shfl_xor_sync(0xffffffffu, b0, off);
            }
            rA[mt] = a0; rB[mt] = b0;
        }
        float cs[4][2];
#pragma unroll
        for (int nt = 0; nt < 4; nt++)
#pragma unroll
            for (int j = 0; j < 2; j++) {
                float v = acc[0][nt][j] + acc[0][nt][j + 2]
                        + acc[1][nt][j] + acc[1][nt][j + 2];
#pragma unroll
                for (int off = 4; off <= 16; off <<= 1)
                    v += __shfl_xor_sync(0xffffffffu, v, off);
                cs[nt][j] = v;
            }

        float* pm = spm + (w * 16 + q) * MPAD;
        float* pl = spl + (w * 16 + q) * MPAD;
        if (t == 0) {
            pm[g]      = rA[0] * inv;
            pm[g + 8]  = rB[0] * inv;
            pm[g + 16] = rA[1] * inv;
            pm[g + 24] = rB[1] * inv;
        }
        if (g == 0) {
#pragma unroll
            for (int nt = 0; nt < 4; nt++) {
                pl[nt * 8 + 2 * t]     = cs[nt][0] * inv;
                pl[nt * 8 + 2 * t + 1] = cs[nt][1] * inv;
            }
        }
    }
    __syncthreads();

    // epilogue: all 16 warps; w = q>>3, nt = q&7; store into fp16 A-frag zp
    {
        const int w  = q >> 3;
        const int nt = q & 7;
        const int ro = 16 * w;
        float zacc[4] = {0.f, 0.f, 0.f, 0.f};
#pragma unroll
        for (int term = 0; term < 2; term++) {
            const float* P = (term ? spl : spm) + (w * 16) * MPAD;
            const float* V = (term ? se : sd) + ro * SPAD;
#pragma unroll
            for (int ks = 0; ks < 4; ks++) {
                const int k0 = ks * 8;
                unsigned af[4], bf[2];
                af[0] = f2tf32(P[g * MPAD + k0 + t]);
                af[1] = f2tf32(P[(g + 8) * MPAD + k0 + t]);
                af[2] = f2tf32(P[g * MPAD + k0 + t + 4]);
                af[3] = f2tf32(P[(g + 8) * MPAD + k0 + t + 4]);
                bf[0] = f2tf32(V[(k0 + t) * SPAD + nt * 8 + g]);
                bf[1] = f2tf32(V[(k0 + t + 4) * SPAD + nt * 8 + g]);
                mma_tf32(zacc, af, bf);
            }
        }
        // zacc: (row0,col0),(row0,col0+1),(row0+8,col0),(row0+8,col0+1)
        const int row0 = b * TT + (2 * p + w) * WIN + g;    // row0 & 15 = g (<8)
        const int col0 = h * DH + nt * 8 + 2 * t;
        const int stripe = row0 >> 7;
        const int ii     = (row0 >> 4) & 7;
        const int gq     = row0 & 7;
        const int ksi    = col0 >> 4;
        const int cc     = col0 & 15;
        const int hi8    = cc >> 3;
        const size_t qi = ((size_t)(stripe * 48 + ksi) * 8 + ii) * 32 + gq * 4 + t;
        uint2 val;
        val.x = h2u(__floats2half2_rn(zacc[0], zacc[1]));
        val.y = h2u(__floats2half2_rn(zacc[2], zacc[3]));
        *(uint2*)((char*)g_zp + qi * 16 + hi8 * 8) = val;
    }
}

// ---------------------------------------------------------------------------
extern "C" void kernel_launch(void* const* d_in, const int* in_sizes, int n_in,
                              void* d_out, int out_size)
{
    const float* x  = (const float*)d_in[0];  // (2,2048,768)
    const float* W1 = (const float*)d_in[1];  // (768, 3840)
    const float* b1 = (const float*)d_in[2];  // (3840)
    const float* WO = (const float*)d_in[3];  // (768, 768)
    const float* bO = (const float*)d_in[4];  // (768)
    float* out = (float*)d_out;               // (2,2048,768)

    float *abcde, *xp, *zp, *w1p, *wop;
    cudaGetSymbolAddress((void**)&abcde, g_abcde);
    cudaGetSymbolAddress((void**)&xp,    g_xp);
    cudaGetSymbolAddress((void**)&zp,    g_zp);
    cudaGetSymbolAddress((void**)&w1p,   g_w1p);
    cudaGetSymbolAddress((void**)&wop,   g_wop);

    cudaFuncSetAttribute(gemm_h,
                         cudaFuncAttributeMaxDynamicSharedMemorySize, GSMEM);
    cudaFuncSetAttribute(gemm_h64,
                         cudaFuncAttributeMaxDynamicSharedMemorySize, GSMEM64);
    cudaFuncSetAttribute(attn_kernel,
                         cudaFuncAttributeMaxDynamicSharedMemorySize, ASMEM);

    const int M  = BB * TT;          // 4096
    const int N1 = 5 * NH * DH;      // 3840
    const int N2 = DMODEL;           // 768
    const int K  = DMODEL;           // 768

    // 0) all operand packing (fp16 fragments) in one launch
    pack_all<<<1536 + 1440 + 288, 256>>>(x, W1, WO);

    // 1) abcde = x @ W1 + b1   (fp16 tensor cores)
    gemm_h<<<dim3(N1 / 128, M / 128), 256, GSMEM>>>(xp, w1p, b1, abcde, M, N1, K);

    // 2) local trittention (2 windows/block) -> zp (fp16 A-frag)
    attn_kernel<<<BB * NH * (NWIN / 2), 512, ASMEM>>>();

    // 3) out = z @ WO + bO  (fp16, 64-row tiles)
    gemm_h64<<<dim3(N2 / 128, M / 64), 256, GSMEM64>>>(zp, wop, bO, out, M, N2, K);
}